// round 14
// baseline (speedup 1.0000x reference)
#include <cuda_runtime.h>
#include <math.h>

#define BATCH 4
#define NPTS  4096
#define M1    2048
#define M2    410
#define KNN   64
#define R2 (BATCH*M2*KNN)   /* 104960 */
#define R3 (BATCH*M2)       /* 1640   */

// ---------------- static scratch (no allocations allowed) ----------------
__device__ float g_qpos1[BATCH*M1*3];
__device__ float g_qpos2[BATCH*M2*3];
__device__ int   g_nidx2[R2];
__device__ float g_nd2_2[R2];
__device__ float g_x1[BATCH*M1*128];
__device__ float g_x2[BATCH*M2*512];
__device__ float g_glob[BATCH*1024];
__device__ float g_bufX[13749760];   // max(R2*131, R3*515)
__device__ float g_bufA[13762560];   // max(R2*128, R3*1024)
__device__ int   g_prog[BATCH];      // fps1 progress counters

// ---------------- packed f32x2 helpers ----------------
__device__ __forceinline__ unsigned long long pack2(float lo, float hi) {
    unsigned long long r;
    asm("mov.b64 %0, {%1, %2};" : "=l"(r) : "f"(lo), "f"(hi));
    return r;
}
__device__ __forceinline__ void unpack2(unsigned long long v, float& lo, float& hi) {
    asm("mov.b64 {%0, %1}, %2;" : "=f"(lo), "=f"(hi) : "l"(v));
}
__device__ __forceinline__ unsigned long long add2(unsigned long long a, unsigned long long b) {
    unsigned long long r; asm("add.rn.f32x2 %0, %1, %2;" : "=l"(r) : "l"(a), "l"(b)); return r;
}
__device__ __forceinline__ unsigned long long mul2(unsigned long long a, unsigned long long b) {
    unsigned long long r; asm("mul.rn.f32x2 %0, %1, %2;" : "=l"(r) : "l"(a), "l"(b)); return r;
}

__global__ void init_prog()
{
    if (threadIdx.x < BATCH) *(volatile int*)&g_prog[threadIdx.x] = 0;
}

// =====================================================================
// Round-11 FPS (best measured). One block per batch, 256 threads, PTS
// contiguous points/thread in packed f32x2 registers. Two barriers:
// redux.max -> STS -> bar -> 8-way max -> candidate rescan ->
// smem atomicMax key (it<<12)|(4095-idx) -> bar -> broadcast LDG.
// jnp-exact: dx=x+(-lx); (dx*dx+dy*dy)+dz*dz; fmin; argmax first-index.
// Used for fps2 only (fps1 lives in sa1_mega).
// =====================================================================
template<int PTS>
__global__ void __launch_bounds__(256) fps_fast(const float* __restrict__ pos,
                                                int n, int m,
                                                float* __restrict__ qpos)
{
    constexpr int PAIRS = PTS / 2;
    __shared__ unsigned s_wv[8];
    __shared__ int s_key;

    const int b = blockIdx.x;
    const float* P = pos + (size_t)b * n * 3;
    float* Q = qpos + (size_t)b * m * 3;
    const int tid = threadIdx.x;
    const int lane = tid & 31, wid = tid >> 5;
    const int base = tid * PTS;

    unsigned long long px2[PAIRS], py2[PAIRS], pz2[PAIRS];
    float md[PTS];
#pragma unroll
    for (int j = 0; j < PAIRS; j++) {
        const float* p0 = P + (size_t)(base + 2*j) * 3;
        px2[j] = pack2(p0[0], p0[3]);
        py2[j] = pack2(p0[1], p0[4]);
        pz2[j] = pack2(p0[2], p0[5]);
    }
#pragma unroll
    for (int j = 0; j < PTS; j++) md[j] = __int_as_float(0x7f800000);

    if (tid == 0) s_key = -1;
    __syncthreads();

    float lx = P[0], ly = P[1], lz = P[2];
    if (tid == 0) { Q[0] = lx; Q[1] = ly; Q[2] = lz; }

    for (int it = 1; it < m; it++) {
        unsigned long long nlx = pack2(-lx, -lx);
        unsigned long long nly = pack2(-ly, -ly);
        unsigned long long nlz = pack2(-lz, -lz);
        float bmA = -1.f, bmB = -1.f;
#pragma unroll
        for (int j = 0; j < PAIRS; j++) {
            unsigned long long dx = add2(px2[j], nlx);
            unsigned long long dy = add2(py2[j], nly);
            unsigned long long dz = add2(pz2[j], nlz);
            unsigned long long s = add2(add2(mul2(dx,dx), mul2(dy,dy)), mul2(dz,dz));
            float lo, hi; unpack2(s, lo, hi);
            float m0 = fminf(md[2*j],   lo); md[2*j]   = m0;
            float m1 = fminf(md[2*j+1], hi); md[2*j+1] = m1;
            bmA = fmaxf(bmA, m0);
            bmB = fmaxf(bmB, m1);
        }
        float bm = fmaxf(bmA, bmB);
        unsigned vm = __reduce_max_sync(0xffffffffu, __float_as_uint(bm));
        if (lane == 0) s_wv[wid] = vm;
        __syncthreads();
        unsigned gv = max(max(max(s_wv[0], s_wv[1]), max(s_wv[2], s_wv[3])),
                          max(max(s_wv[4], s_wv[5]), max(s_wv[6], s_wv[7])));
        if (__float_as_uint(bm) == gv) {
            int loc = PTS;
#pragma unroll
            for (int j = PTS - 1; j >= 0; j--)
                if (__float_as_uint(md[j]) == gv) loc = j;
            if (loc < PTS) atomicMax(&s_key, (it << 12) | (4095 - (base + loc)));
        }
        __syncthreads();
        int gi = 4095 - (s_key & 4095);
        const float* pw = P + (size_t)gi * 3;
        lx = pw[0]; ly = pw[1]; lz = pw[2];
        if (tid == 0) {
            Q[(size_t)it*3]   = lx;
            Q[(size_t)it*3+1] = ly;
            Q[(size_t)it*3+2] = lz;
        }
    }
}

// =====================================================================
// MEGA KERNEL: fps1 producer (blocks 0..3) + per-query knn+SA1 consumer
// (blocks 4..4+8191). Consumers poll g_prog[b] until their query is
// produced, then run exact 64-NN radix select (results in SMEM) and the
// fused PointConv (Lin6x64+ReLU+BN -> Lin64x64+ReLU+BN -> dual-radius
// masked max) writing g_x1[bq][128].
// Coherence: qpos1 read with __ldcg (L2) — plain LDG could hit a stale
// L1 line spanning ~10 adjacent queries. Ordering: producer STG coords
// -> __threadfence -> volatile prog store; consumer volatile poll ->
// __threadfence -> __syncthreads.
// Launched with ~120KB dummy dynamic smem => 1 block/SM so the 4
// producer SMs run uncontended.
// =====================================================================
__global__ void __launch_bounds__(256) sa1_mega(
    const float* __restrict__ xyz, const float* __restrict__ color,
    const float* __restrict__ w1a, const float* __restrict__ b1a,
    const float* __restrict__ g1a, const float* __restrict__ be1a,
    const float* __restrict__ w1b, const float* __restrict__ b1b,
    const float* __restrict__ g1b, const float* __restrict__ be1b)
{
    extern __shared__ char occupancy_pad[];   // unused; limits blocks/SM
    const int tid = threadIdx.x;

    // ---------------- producer role: fps1 ----------------
    if (blockIdx.x < BATCH) {
        constexpr int PTS = 16, PAIRS = 8;
        __shared__ unsigned s_wv[8];
        __shared__ int s_key;
        const int b = blockIdx.x;
        const float* P = xyz + (size_t)b * NPTS * 3;
        float* Q = g_qpos1 + (size_t)b * M1 * 3;
        const int lane = tid & 31, wid = tid >> 5;
        const int base = tid * PTS;

        unsigned long long px2[PAIRS], py2[PAIRS], pz2[PAIRS];
        float md[PTS];
#pragma unroll
        for (int j = 0; j < PAIRS; j++) {
            const float* p0 = P + (size_t)(base + 2*j) * 3;
            px2[j] = pack2(p0[0], p0[3]);
            py2[j] = pack2(p0[1], p0[4]);
            pz2[j] = pack2(p0[2], p0[5]);
        }
#pragma unroll
        for (int j = 0; j < PTS; j++) md[j] = __int_as_float(0x7f800000);

        if (tid == 0) s_key = -1;
        __syncthreads();

        float lx = P[0], ly = P[1], lz = P[2];
        if (tid == 0) {
            Q[0] = lx; Q[1] = ly; Q[2] = lz;
            __threadfence();
            *(volatile int*)&g_prog[b] = 1;
        }

        for (int it = 1; it < M1; it++) {
            unsigned long long nlx = pack2(-lx, -lx);
            unsigned long long nly = pack2(-ly, -ly);
            unsigned long long nlz = pack2(-lz, -lz);
            float bmA = -1.f, bmB = -1.f;
#pragma unroll
            for (int j = 0; j < PAIRS; j++) {
                unsigned long long dx = add2(px2[j], nlx);
                unsigned long long dy = add2(py2[j], nly);
                unsigned long long dz = add2(pz2[j], nlz);
                unsigned long long s = add2(add2(mul2(dx,dx), mul2(dy,dy)), mul2(dz,dz));
                float lo, hi; unpack2(s, lo, hi);
                float m0 = fminf(md[2*j],   lo); md[2*j]   = m0;
                float m1 = fminf(md[2*j+1], hi); md[2*j+1] = m1;
                bmA = fmaxf(bmA, m0);
                bmB = fmaxf(bmB, m1);
            }
            float bm = fmaxf(bmA, bmB);
            unsigned vm = __reduce_max_sync(0xffffffffu, __float_as_uint(bm));
            if (lane == 0) s_wv[wid] = vm;
            __syncthreads();
            unsigned gv = max(max(max(s_wv[0], s_wv[1]), max(s_wv[2], s_wv[3])),
                              max(max(s_wv[4], s_wv[5]), max(s_wv[6], s_wv[7])));
            if (__float_as_uint(bm) == gv) {
                int loc = PTS;
#pragma unroll
                for (int j = PTS - 1; j >= 0; j--)
                    if (__float_as_uint(md[j]) == gv) loc = j;
                if (loc < PTS) atomicMax(&s_key, (it << 12) | (4095 - (base + loc)));
            }
            __syncthreads();
            int gi = 4095 - (s_key & 4095);
            const float* pw = P + (size_t)gi * 3;
            lx = pw[0]; ly = pw[1]; lz = pw[2];
            if (tid == 0) {
                Q[(size_t)it*3]   = lx;
                Q[(size_t)it*3+1] = ly;
                Q[(size_t)it*3+2] = lz;
                __threadfence();
                *(volatile int*)&g_prog[b] = it + 1;
            }
        }
        return;
    }

    // ---------------- consumer role: knn + SA1 for one query ----------------
    const int bq = blockIdx.x - BATCH;     // 0..8191
    const int b  = bq >> 11;
    const int q  = bq & (M1 - 1);
    const float bnf = 1.0f / sqrtf(1.0f + 1e-5f);

    // knn smem
    __shared__ unsigned bins[256];
    __shared__ unsigned s_b, s_r;
    __shared__ int s_cnt, s_last;
    __shared__ unsigned s_min;
    __shared__ int   s_nidx[64];
    __shared__ float s_nd2[64];
    // sa smem
    __shared__ __align__(16) float feats[64][6];
    __shared__ __align__(16) float Xs[64][66];
    __shared__ __align__(16) float Ws[64][66];
    __shared__ float redA[8][64];
    __shared__ float redB[8][64];

    // stage w1b while waiting (independent of producer)
    for (int i = tid; i < 4096; i += 256) Ws[i >> 6][i & 63] = w1b[i];

    if (tid == 0) {
        while (*(volatile int*)&g_prog[b] <= q) __nanosleep(64);
        __threadfence();
    }
    __syncthreads();

    // ---- exact 64-NN radix select (EPT=16, n=4096) ----
    const float* S = xyz + (size_t)b * NPTS * 3;
    float qx = __ldcg(&g_qpos1[(size_t)bq*3]);
    float qy = __ldcg(&g_qpos1[(size_t)bq*3 + 1]);
    float qz = __ldcg(&g_qpos1[(size_t)bq*3 + 2]);
    unsigned rb[16];
#pragma unroll
    for (int j = 0; j < 16; j++) {
        int i = j*256 + tid;
        float dx = __fadd_rn(S[i*3],   -qx);
        float dy = __fadd_rn(S[i*3+1], -qy);
        float dz = __fadd_rn(S[i*3+2], -qz);
        rb[j] = __float_as_uint(__fadd_rn(__fadd_rn(__fmul_rn(dx,dx), __fmul_rn(dy,dy)),
                                          __fmul_rn(dz,dz)));
    }

    unsigned prefix = 0;
    unsigned rank = 64;
#pragma unroll
    for (int pass = 0; pass < 4; pass++) {
        const int shift = 24 - 8*pass;
        bins[tid] = 0;
        __syncthreads();
#pragma unroll
        for (int j = 0; j < 16; j++) {
            unsigned v = rb[j];
            bool in = (pass == 0) ? true : ((v >> (shift + 8)) == prefix);
            if (in) atomicAdd(&bins[(v >> shift) & 255], 1u);
        }
        __syncthreads();
        if (tid < 32) {
            unsigned c[8]; unsigned ssum = 0;
#pragma unroll
            for (int t = 0; t < 8; t++) { c[t] = bins[tid*8 + t]; ssum += c[t]; }
            unsigned cum = ssum;
#pragma unroll
            for (int off = 1; off < 32; off <<= 1) {
                unsigned o = __shfl_up_sync(0xffffffffu, cum, off);
                if (tid >= off) cum += o;
            }
            unsigned excl = cum - ssum;
            if (rank > excl && rank <= cum) {
                unsigned rr = rank - excl;
#pragma unroll
                for (int t = 0; t < 8; t++) {
                    if (rr <= c[t]) { s_b = (unsigned)(tid*8 + t); s_r = rr; break; }
                    rr -= c[t];
                }
            }
        }
        __syncthreads();
        prefix = (prefix << 8) | s_b;
        rank = s_r;
        __syncthreads();
    }

    const unsigned T = prefix;
    const int take = (int)rank;

    if (tid == 0) { s_cnt = 0; s_last = -1; }
    __syncthreads();
#pragma unroll
    for (int j = 0; j < 16; j++) {
        if (rb[j] < T) {
            int slot = atomicAdd(&s_cnt, 1);
            s_nidx[slot] = j*256 + tid;
            s_nd2 [slot] = __uint_as_float(rb[j]);
        }
    }
    __syncthreads();
    const int c_less = s_cnt;
    for (int t = 0; t < take; t++) {
        if (tid == 0) s_min = 0xffffffffu;
        __syncthreads();
        int last = s_last;
#pragma unroll
        for (int j = 0; j < 16; j++) {
            int i = j*256 + tid;
            if (rb[j] == T && i > last) atomicMin(&s_min, (unsigned)i);
        }
        __syncthreads();
        if (tid == 0) {
            int win = (int)s_min;
            s_last = win;
            s_nidx[c_less + t] = win;
            s_nd2 [c_less + t] = __uint_as_float(T);
        }
        __syncthreads();
    }

    // ---- fused SA1 PointConv ----
    if (tid < 64) {
        int pt = s_nidx[tid];
        const float* cb = color + ((size_t)b*NPTS + pt) * 3;
        const float* pb = xyz   + ((size_t)b*NPTS + pt) * 3;
        feats[tid][0] = cb[0]; feats[tid][1] = cb[1]; feats[tid][2] = cb[2];
        feats[tid][3] = pb[0] - qx;
        feats[tid][4] = pb[1] - qy;
        feats[tid][5] = pb[2] - qz;
    }
    __syncthreads();

    if (tid < 128) {
        int row = tid >> 1;
        int cb0 = (tid & 1) * 32;
        float f0 = feats[row][0], f1 = feats[row][1], f2 = feats[row][2];
        float f3 = feats[row][3], f4 = feats[row][4], f5 = feats[row][5];
#pragma unroll 8
        for (int c = 0; c < 32; c++) {
            int col = cb0 + c;
            float acc = 0.f;
            acc = fmaf(f0, w1a[col],        acc);
            acc = fmaf(f1, w1a[64  + col],  acc);
            acc = fmaf(f2, w1a[128 + col],  acc);
            acc = fmaf(f3, w1a[192 + col],  acc);
            acc = fmaf(f4, w1a[256 + col],  acc);
            acc = fmaf(f5, w1a[320 + col],  acc);
            float v = fmaxf(acc + b1a[col], 0.f);
            Xs[col][row] = v * (g1a[col] * bnf) + be1a[col];
        }
    }
    __syncthreads();

    if (tid < 128) {
        const int tn = (tid & 15) * 4;
        const int tm = (tid >> 4) * 8;
        unsigned long long acc[4][4];
#pragma unroll
        for (int i = 0; i < 4; i++)
#pragma unroll
            for (int j = 0; j < 4; j++) acc[i][j] = 0ull;

#pragma unroll 4
        for (int k = 0; k < 64; k++) {
            unsigned long long a2[4], b2[4];
#pragma unroll
            for (int i = 0; i < 4; i++)
                a2[i] = *(const unsigned long long*)&Xs[k][tm + 2*i];
#pragma unroll
            for (int j = 0; j < 4; j++) {
                float bv = Ws[k][tn + j];
                asm("mov.b64 %0, {%1, %1};" : "=l"(b2[j]) : "f"(bv));
            }
#pragma unroll
            for (int i = 0; i < 4; i++)
#pragma unroll
                for (int j = 0; j < 4; j++)
                    asm("fma.rn.f32x2 %0, %1, %2, %0;"
                        : "+l"(acc[i][j]) : "l"(a2[i]), "l"(b2[j]));
        }

        const float rA = (float)(0.2*0.2), rB = (float)(0.1*0.1);
        const float NEG = -3.402823466e38f;
#pragma unroll
        for (int j = 0; j < 4; j++) {
            int col = tn + j;
            float s = g1b[col] * bnf, t = be1b[col], bi = b1b[col];
            float mA = NEG, mB = NEG;
#pragma unroll
            for (int i = 0; i < 4; i++) {
                float lo, hi; unpack2(acc[i][j], lo, hi);
                int r0 = tm + 2*i;
                float vlo = fmaxf(lo + bi, 0.f) * s + t;
                float vhi = fmaxf(hi + bi, 0.f) * s + t;
                float dA = s_nd2[r0], dB = s_nd2[r0+1];
                if (dA <= rA) mA = fmaxf(mA, vlo);
                if (dA <= rB) mB = fmaxf(mB, vlo);
                if (dB <= rA) mA = fmaxf(mA, vhi);
                if (dB <= rB) mB = fmaxf(mB, vhi);
            }
            redA[tid >> 4][col] = mA;
            redB[tid >> 4][col] = mB;
        }
    }
    __syncthreads();
    if (tid < 64) {
        const float NEG = -3.402823466e38f;
        float a = NEG, c = NEG;
#pragma unroll
        for (int g = 0; g < 8; g++) {
            a = fmaxf(a, redA[g][tid]);
            c = fmaxf(c, redB[g][tid]);
        }
        g_x1[(size_t)bq*128 + tid]      = (a > -1e30f) ? a : 0.f;
        g_x1[(size_t)bq*128 + 64 + tid] = (c > -1e30f) ? c : 0.f;
    }
}

// =====================================================================
// Exact 64-NN SET per query via radix select (global outputs) — knn2.
// =====================================================================
template<int EPT>
__global__ void __launch_bounds__(256) knn_select(const float* __restrict__ src,
                                                  const float* __restrict__ qpos,
                                                  int m,
                                                  int* __restrict__ nidx,
                                                  float* __restrict__ nd2)
{
    __shared__ unsigned bins[256];
    __shared__ unsigned s_b, s_r;
    __shared__ int s_cnt;
    __shared__ int s_last;
    __shared__ unsigned s_min;

    const int n = EPT * 256;
    const int bq = blockIdx.x;
    const int b  = bq / m;
    const float* S = src + (size_t)b * n * 3;
    const int tid = threadIdx.x;

    float qx = qpos[(size_t)bq*3], qy = qpos[(size_t)bq*3+1], qz = qpos[(size_t)bq*3+2];
    unsigned rb[EPT];
#pragma unroll
    for (int j = 0; j < EPT; j++) {
        int i = j*256 + tid;
        float dx = __fadd_rn(S[i*3],   -qx);
        float dy = __fadd_rn(S[i*3+1], -qy);
        float dz = __fadd_rn(S[i*3+2], -qz);
        rb[j] = __float_as_uint(__fadd_rn(__fadd_rn(__fmul_rn(dx,dx), __fmul_rn(dy,dy)),
                                          __fmul_rn(dz,dz)));
    }

    unsigned prefix = 0;
    unsigned rank = 64;
#pragma unroll
    for (int pass = 0; pass < 4; pass++) {
        const int shift = 24 - 8*pass;
        bins[tid] = 0;
        __syncthreads();
#pragma unroll
        for (int j = 0; j < EPT; j++) {
            unsigned v = rb[j];
            bool in = (pass == 0) ? true : ((v >> (shift + 8)) == prefix);
            if (in) atomicAdd(&bins[(v >> shift) & 255], 1u);
        }
        __syncthreads();
        if (tid < 32) {
            unsigned c[8]; unsigned ssum = 0;
#pragma unroll
            for (int t = 0; t < 8; t++) { c[t] = bins[tid*8 + t]; ssum += c[t]; }
            unsigned cum = ssum;
#pragma unroll
            for (int off = 1; off < 32; off <<= 1) {
                unsigned o = __shfl_up_sync(0xffffffffu, cum, off);
                if (tid >= off) cum += o;
            }
            unsigned excl = cum - ssum;
            if (rank > excl && rank <= cum) {
                unsigned rr = rank - excl;
#pragma unroll
                for (int t = 0; t < 8; t++) {
                    if (rr <= c[t]) { s_b = (unsigned)(tid*8 + t); s_r = rr; break; }
                    rr -= c[t];
                }
            }
        }
        __syncthreads();
        prefix = (prefix << 8) | s_b;
        rank = s_r;
        __syncthreads();
    }

    const unsigned T = prefix;
    const int take = (int)rank;

    if (tid == 0) { s_cnt = 0; s_last = -1; }
    __syncthreads();
#pragma unroll
    for (int j = 0; j < EPT; j++) {
        if (rb[j] < T) {
            int slot = atomicAdd(&s_cnt, 1);
            int i = j*256 + tid;
            nidx[(size_t)bq*KNN + slot] = i;
            nd2 [(size_t)bq*KNN + slot] = __uint_as_float(rb[j]);
        }
    }
    __syncthreads();
    const int c_less = s_cnt;
    for (int t = 0; t < take; t++) {
        if (tid == 0) s_min = 0xffffffffu;
        __syncthreads();
        int last = s_last;
#pragma unroll
        for (int j = 0; j < EPT; j++) {
            int i = j*256 + tid;
            if (rb[j] == T && i > last) atomicMin(&s_min, (unsigned)i);
        }
        __syncthreads();
        if (tid == 0) {
            int win = (int)s_min;
            s_last = win;
            nidx[(size_t)bq*KNN + c_less + t] = win;
            nd2 [(size_t)bq*KNN + c_less + t] = __uint_as_float(T);
        }
        __syncthreads();
    }
}

// =====================================================================
// Gather kernels for SA2 / mlp3 inputs
// =====================================================================
__global__ void gather2_kernel()
{
    int gt = blockIdx.x * 256 + threadIdx.x;
    int w = gt >> 5, lane = gt & 31;
    if (w >= R2) return;
    int b = w / (M2 * KNN);
    int q = (w / KNN) % M2;
    int n = g_nidx2[w];
    const float* xr = g_x1 + ((size_t)(b*M1 + n)) * 128;
    float* o = g_bufX + (size_t)w * 131;
#pragma unroll
    for (int i = 0; i < 4; i++) o[lane + 32*i] = xr[lane + 32*i];
    if (lane < 3)
        o[128 + lane] = g_qpos1[((size_t)(b*M1 + n))*3 + lane]
                      - g_qpos2[((size_t)(b*M2 + q))*3 + lane];
}

__global__ void gather3_kernel()
{
    int e = blockIdx.x * 256 + threadIdx.x;
    if (e >= R3 * 515) return;
    int row = e / 515, c = e % 515;
    g_bufX[e] = (c < 512) ? g_x2[(size_t)row*512 + c]
                          : g_qpos2[(size_t)row*3 + (c - 512)];
}

// =====================================================================
// Tiled SGEMM Y = bn(relu(X @ W + bias)) with packed fma.rn.f32x2.
// =====================================================================
#define BKK 16
__global__ void __launch_bounds__(128) gemm_bn(const float* __restrict__ X,
    const float* __restrict__ W, const float* __restrict__ bias,
    const float* __restrict__ gamma, const float* __restrict__ beta,
    float* __restrict__ Y, int M, int K, int N)
{
    __shared__ __align__(16) float As[BKK][64 + 4];
    __shared__ __align__(16) float Bs[BKK][64 + 4];
    const int tid = threadIdx.x;
    const int bm = blockIdx.y * 64, bn = blockIdx.x * 64;
    const int tn = (tid & 15) * 4;
    const int tm = (tid >> 4) * 8;

    unsigned long long acc[4][4];
#pragma unroll
    for (int i = 0; i < 4; i++)
#pragma unroll
        for (int j = 0; j < 4; j++) acc[i][j] = 0ull;

    for (int k0 = 0; k0 < K; k0 += BKK) {
#pragma unroll
        for (int i = 0; i < 8; i++) {
            int t = i*128 + tid;
            int m = t >> 4, k = t & 15;
            float v = 0.f;
            int gr = bm + m, gk = k0 + k;
            if (gr < M && gk < K) v = X[(size_t)gr*K + gk];
            As[k][m] = v;
        }
#pragma unroll
        for (int i = 0; i < 8; i++) {
            int t = i*128 + tid;
            int k = t >> 6, n = t & 63;
            float v = 0.f;
            int gk = k0 + k;
            if (gk < K) v = W[(size_t)gk*N + bn + n];
            Bs[k][n] = v;
        }
        __syncthreads();
#pragma unroll
        for (int kk = 0; kk < BKK; kk++) {
            unsigned long long a2[4], b2[4];
#pragma unroll
            for (int i = 0; i < 4; i++)
                a2[i] = *(const unsigned long long*)&As[kk][tm + 2*i];
#pragma unroll
            for (int j = 0; j < 4; j++) {
                float bv = Bs[kk][tn + j];
                asm("mov.b64 %0, {%1, %1};" : "=l"(b2[j]) : "f"(bv));
            }
#pragma unroll
            for (int i = 0; i < 4; i++)
#pragma unroll
                for (int j = 0; j < 4; j++)
                    asm("fma.rn.f32x2 %0, %1, %2, %0;"
                        : "+l"(acc[i][j]) : "l"(a2[i]), "l"(b2[j]));
        }
        __syncthreads();
    }

    const float bnf = 1.0f / sqrtf(1.0f + 1e-5f);
    float s[4], t[4], bi[4];
#pragma unroll
    for (int j = 0; j < 4; j++) {
        int c = bn + tn + j;
        s[j] = gamma[c] * bnf; t[j] = beta[c]; bi[j] = bias[c];
    }
#pragma unroll
    for (int i = 0; i < 4; i++) {
#pragma unroll
        for (int j = 0; j < 4; j++) {
            float lo, hi; unpack2(acc[i][j], lo, hi);
            int r0 = bm + tm + 2*i;
            if (r0 < M) {
                float v = fmaxf(lo + bi[j], 0.f);
                Y[(size_t)r0*N + bn + tn + j] = v * s[j] + t[j];
            }
            if (r0 + 1 < M) {
                float v = fmaxf(hi + bi[j], 0.f);
                Y[(size_t)(r0+1)*N + bn + tn + j] = v * s[j] + t[j];
            }
        }
    }
}

// =====================================================================
// SA2 layer-2 GEMM (K=128, N=256) with FUSED dual-radius masked max.
// =====================================================================
__global__ void __launch_bounds__(128) gemm_bn_max2(const float* __restrict__ X,
    const float* __restrict__ W, const float* __restrict__ bias,
    const float* __restrict__ gamma, const float* __restrict__ beta)
{
    __shared__ __align__(16) float As[BKK][64 + 4];
    __shared__ __align__(16) float Bs[BKK][64 + 4];
    __shared__ float d2s[64];
    __shared__ float redA[8][64];
    __shared__ float redB[8][64];
    const int K = 128, N = 256;
    const int tid = threadIdx.x;
    const int bq = blockIdx.y;
    const int bm = bq * 64, bn = blockIdx.x * 64;
    const int tn = (tid & 15) * 4;
    const int tm = (tid >> 4) * 8;

    if (tid < 64) d2s[tid] = g_nd2_2[(size_t)bq*KNN + tid];

    unsigned long long acc[4][4];
#pragma unroll
    for (int i = 0; i < 4; i++)
#pragma unroll
        for (int j = 0; j < 4; j++) acc[i][j] = 0ull;

    for (int k0 = 0; k0 < K; k0 += BKK) {
#pragma unroll
        for (int i = 0; i < 8; i++) {
            int t = i*128 + tid;
            int m = t >> 4, k = t & 15;
            As[k][m] = X[(size_t)(bm + m)*K + k0 + k];
        }
#pragma unroll
        for (int i = 0; i < 8; i++) {
            int t = i*128 + tid;
            int k = t >> 6, n = t & 63;
            Bs[k][n] = W[(size_t)(k0 + k)*N + bn + n];
        }
        __syncthreads();
#pragma unroll
        for (int kk = 0; kk < BKK; kk++) {
            unsigned long long a2[4], b2[4];
#pragma unroll
            for (int i = 0; i < 4; i++)
                a2[i] = *(const unsigned long long*)&As[kk][tm + 2*i];
#pragma unroll
            for (int j = 0; j < 4; j++) {
                float bv = Bs[kk][tn + j];
                asm("mov.b64 %0, {%1, %1};" : "=l"(b2[j]) : "f"(bv));
            }
#pragma unroll
            for (int i = 0; i < 4; i++)
#pragma unroll
                for (int j = 0; j < 4; j++)
                    asm("fma.rn.f32x2 %0, %1, %2, %0;"
                        : "+l"(acc[i][j]) : "l"(a2[i]), "l"(b2[j]));
        }
        __syncthreads();
    }

    const float bnf = 1.0f / sqrtf(1.0f + 1e-5f);
    const float rA = (float)(0.35*0.35), rB = (float)(0.5*0.5);
    const float NEG = -3.402823466e38f;
#pragma unroll
    for (int j = 0; j < 4; j++) {
        int c = bn + tn + j;
        float s = gamma[c] * bnf, t = beta[c], bi = bias[c];
        float mA = NEG, mB = NEG;
#pragma unroll
        for (int i = 0; i < 4; i++) {
            float lo, hi; unpack2(acc[i][j], lo, hi);
            int r0 = tm + 2*i;
            float vlo = fmaxf(lo + bi, 0.f) * s + t;
            float vhi = fmaxf(hi + bi, 0.f) * s + t;
            float dA = d2s[r0], dB = d2s[r0+1];
            if (dA <= rA) mA = fmaxf(mA, vlo);
            if (dA <= rB) mB = fmaxf(mB, vlo);
            if (dB <= rA) mA = fmaxf(mA, vhi);
            if (dB <= rB) mB = fmaxf(mB, vhi);
        }
        redA[tid >> 4][tn + j] = mA;
        redB[tid >> 4][tn + j] = mB;
    }
    __syncthreads();
    if (tid < 64) {
        float a = NEG, c = NEG;
#pragma unroll
        for (int g = 0; g < 8; g++) {
            a = fmaxf(a, redA[g][tid]);
            c = fmaxf(c, redB[g][tid]);
        }
        g_x2[(size_t)bq*512 + bn + tid]       = (a > -1e30f) ? a : 0.f;
        g_x2[(size_t)bq*512 + 256 + bn + tid] = (c > -1e30f) ? c : 0.f;
    }
}

__global__ void globalmax_kernel()
{
    int f = blockIdx.x * 256 + threadIdx.x;
    int b = blockIdx.y;
    float m = -3.402823466e38f;
    for (int q = 0; q < M2; q++)
        m = fmaxf(m, g_bufA[((size_t)(b*M2 + q))*1024 + f]);
    g_glob[(size_t)b*1024 + f] = m;
}

// =====================================================================
// Head: h1 = relu(g @ wl1 + bl1); out = h1 @ wl2 + bl2; L2-normalize.
// =====================================================================
__global__ void __launch_bounds__(512) head_kernel(
    const float* __restrict__ wl1, const float* __restrict__ bl1,
    const float* __restrict__ wl2, const float* __restrict__ bl2,
    float* __restrict__ out)
{
    __shared__ float sg[1024];
    __shared__ float sh[512];
    __shared__ float so[128];
    __shared__ float snorm;
    int b = blockIdx.x, tid = threadIdx.x;
    sg[tid]       = g_glob[(size_t)b*1024 + tid];
    sg[tid + 512] = g_glob[(size_t)b*1024 + 512 + tid];
    __syncthreads();

    float acc = bl1[tid];
    for (int k = 0; k < 1024; k++) acc = fmaf(sg[k], wl1[(size_t)k*512 + tid], acc);
    sh[tid] = fmaxf(acc, 0.f);
    __syncthreads();

    if (tid < 128) {
        float o = bl2[tid];
        for (int k = 0; k < 512; k++) o = fmaf(sh[k], wl2[(size_t)k*128 + tid], o);
        so[tid] = o;
    }
    __syncthreads();
    if (tid < 32) {
        float s = 0.f;
        for (int c = tid; c < 128; c += 32) s += so[c] * so[c];
#pragma unroll
        for (int off = 16; off > 0; off >>= 1) s += __shfl_down_sync(0xffffffffu, s, off);
        if (tid == 0) snorm = sqrtf(s);
    }
    __syncthreads();
    if (tid < 128) out[(size_t)b*128 + tid] = so[tid] / snorm;
}

// =====================================================================
extern "C" void kernel_launch(void* const* d_in, const int* in_sizes, int n_in,
                              void* d_out, int out_size)
{
    const float* xyz   = (const float*)d_in[0];
    const float* color = (const float*)d_in[1];
    const float* w1a = (const float*)d_in[2],  *b1a = (const float*)d_in[3];
    const float* g1a = (const float*)d_in[4],  *be1a = (const float*)d_in[5];
    const float* w1b = (const float*)d_in[6],  *b1b = (const float*)d_in[7];
    const float* g1b = (const float*)d_in[8],  *be1b = (const float*)d_in[9];
    const float* w2a = (const float*)d_in[10], *b2a = (const float*)d_in[11];
    const float* g2a = (const float*)d_in[12], *be2a = (const float*)d_in[13];
    const float* w2b = (const float*)d_in[14], *b2b = (const float*)d_in[15];
    const float* g2b = (const float*)d_in[16], *be2b = (const float*)d_in[17];
    const float* w3  = (const float*)d_in[18], *b3  = (const float*)d_in[19];
    const float* g3  = (const float*)d_in[20], *be3 = (const float*)d_in[21];
    const float* wl1 = (const float*)d_in[22], *bl1 = (const float*)d_in[23];
    const float* wl2 = (const float*)d_in[24], *bl2 = (const float*)d_in[25];
    float* out = (float*)d_out;

    void *vQ1, *vQ2, *vN2, *vD2, *vX, *vA;
    cudaGetSymbolAddress(&vQ1, g_qpos1);
    cudaGetSymbolAddress(&vQ2, g_qpos2);
    cudaGetSymbolAddress(&vN2, g_nidx2);
    cudaGetSymbolAddress(&vD2, g_nd2_2);
    cudaGetSymbolAddress(&vX, g_bufX);
    cudaGetSymbolAddress(&vA, g_bufA);
    float* aQ1 = (float*)vQ1; float* aQ2 = (float*)vQ2;
    int* aN2 = (int*)vN2; float* aD2 = (float*)vD2;
    float* aX = (float*)vX; float* aA = (float*)vA;

    // occupancy limiter: ~120KB dynamic smem => 1 block/SM in the mega kernel
    static_assert(true, "");
    cudaFuncSetAttribute(sa1_mega, cudaFuncAttributeMaxDynamicSharedMemorySize, 122880);

    // ---- SA module 1: fps1 producer + knn+conv consumers, one kernel ----
    init_prog<<<1, 32>>>();
    sa1_mega<<<BATCH + BATCH*M1, 256, 122880>>>(xyz, color,
                                                w1a, b1a, g1a, be1a,
                                                w1b, b1b, g1b, be1b);

    // ---- SA module 2 ----
    fps_fast<8><<<BATCH, 256>>>(aQ1, M1, M2, aQ2);
    knn_select<8><<<BATCH*M2, 256>>>(aQ1, aQ2, M2, aN2, aD2);
    gather2_kernel<<<(R2*32)/256, 256>>>();
    gemm_bn<<<dim3(2, R2/64), 128>>>(aX, w2a, b2a, g2a, be2a, aA, R2, 131, 128);
    gemm_bn_max2<<<dim3(4, R2/64), 128>>>(aA, w2b, b2b, g2b, be2b);

    // ---- mlp3 + global max + head ----
    gather3_kernel<<<(R3*515 + 255)/256, 256>>>();
    gemm_bn<<<dim3(16, (R3 + 63)/64), 128>>>(aX, w3, b3, g3, be3, aA, R3, 515, 1024);
    globalmax_kernel<<<dim3(4, BATCH), 256>>>();
    head_kernel<<<BATCH, 512>>>(wl1, bl1, wl2, bl2, out);
}

// round 15
// speedup vs baseline: 1.8292x; 1.8292x over previous
#include <cuda_runtime.h>
#include <math.h>

#define BATCH 4
#define NPTS  4096
#define M1    2048
#define M2    410
#define KNN   64
#define R1 (BATCH*M1*KNN)   /* 524288 */
#define R2 (BATCH*M2*KNN)   /* 104960 */
#define R3 (BATCH*M2)       /* 1640   */

// ---------------- static scratch (no allocations allowed) ----------------
__device__ float g_qpos1[BATCH*M1*3];
__device__ float g_qpos2[BATCH*M2*3];
__device__ int   g_nidx1[R1];
__device__ float g_nd2_1[R1];
__device__ int   g_nidx2[R2];
__device__ float g_nd2_2[R2];
__device__ float g_x1[BATCH*M1*128];
__device__ float g_x2[BATCH*M2*512];
__device__ float g_glob[BATCH*1024];
__device__ float g_bufA[13762560];   // max(R2*128, R3*1024)

// ---------------- packed f32x2 helpers ----------------
__device__ __forceinline__ unsigned long long pack2(float lo, float hi) {
    unsigned long long r;
    asm("mov.b64 %0, {%1, %2};" : "=l"(r) : "f"(lo), "f"(hi));
    return r;
}
__device__ __forceinline__ void unpack2(unsigned long long v, float& lo, float& hi) {
    asm("mov.b64 {%0, %1}, %2;" : "=f"(lo), "=f"(hi) : "l"(v));
}
__device__ __forceinline__ unsigned long long add2(unsigned long long a, unsigned long long b) {
    unsigned long long r; asm("add.rn.f32x2 %0, %1, %2;" : "=l"(r) : "l"(a), "l"(b)); return r;
}
__device__ __forceinline__ unsigned long long mul2(unsigned long long a, unsigned long long b) {
    unsigned long long r; asm("mul.rn.f32x2 %0, %1, %2;" : "=l"(r) : "l"(a), "l"(b)); return r;
}

// =====================================================================
// Round-11 FPS body (best measured). 256 threads, PTS contiguous points
// per thread in packed f32x2 registers. redux.max -> STS -> bar ->
// 8-way max -> candidate rescan -> smem atomicMax key -> bar ->
// broadcast LDG. jnp-exact: dx=x+(-lx); (dx*dx+dy*dy)+dz*dz; fmin;
// argmax with first-index ties via key (it<<12)|(4095-idx).
// =====================================================================
template<int PTS>
__device__ __forceinline__ void fps_body(const float* __restrict__ P,
                                         int n, int m, float* __restrict__ Q)
{
    constexpr int PAIRS = PTS / 2;
    __shared__ unsigned s_wv[8];
    __shared__ int s_key;

    const int tid = threadIdx.x;
    const int lane = tid & 31, wid = tid >> 5;
    const int base = tid * PTS;

    unsigned long long px2[PAIRS], py2[PAIRS], pz2[PAIRS];
    float md[PTS];
#pragma unroll
    for (int j = 0; j < PAIRS; j++) {
        const float* p0 = P + (size_t)(base + 2*j) * 3;
        px2[j] = pack2(p0[0], p0[3]);
        py2[j] = pack2(p0[1], p0[4]);
        pz2[j] = pack2(p0[2], p0[5]);
    }
#pragma unroll
    for (int j = 0; j < PTS; j++) md[j] = __int_as_float(0x7f800000);

    if (tid == 0) s_key = -1;
    __syncthreads();

    float lx = P[0], ly = P[1], lz = P[2];
    if (tid == 0) { Q[0] = lx; Q[1] = ly; Q[2] = lz; }

    for (int it = 1; it < m; it++) {
        unsigned long long nlx = pack2(-lx, -lx);
        unsigned long long nly = pack2(-ly, -ly);
        unsigned long long nlz = pack2(-lz, -lz);
        float bmA = -1.f, bmB = -1.f;
#pragma unroll
        for (int j = 0; j < PAIRS; j++) {
            unsigned long long dx = add2(px2[j], nlx);
            unsigned long long dy = add2(py2[j], nly);
            unsigned long long dz = add2(pz2[j], nlz);
            unsigned long long s = add2(add2(mul2(dx,dx), mul2(dy,dy)), mul2(dz,dz));
            float lo, hi; unpack2(s, lo, hi);
            float m0 = fminf(md[2*j],   lo); md[2*j]   = m0;
            float m1 = fminf(md[2*j+1], hi); md[2*j+1] = m1;
            bmA = fmaxf(bmA, m0);
            bmB = fmaxf(bmB, m1);
        }
        float bm = fmaxf(bmA, bmB);   // >= 0: uint compare monotone
        unsigned vm = __reduce_max_sync(0xffffffffu, __float_as_uint(bm));
        if (lane == 0) s_wv[wid] = vm;
        __syncthreads();
        unsigned gv = max(max(max(s_wv[0], s_wv[1]), max(s_wv[2], s_wv[3])),
                          max(max(s_wv[4], s_wv[5]), max(s_wv[6], s_wv[7])));
        if (__float_as_uint(bm) == gv) {
            int loc = PTS;
#pragma unroll
            for (int j = PTS - 1; j >= 0; j--)
                if (__float_as_uint(md[j]) == gv) loc = j;   // keeps smallest j
            if (loc < PTS) atomicMax(&s_key, (it << 12) | (4095 - (base + loc)));
        }
        __syncthreads();
        int gi = 4095 - (s_key & 4095);
        const float* pw = P + (size_t)gi * 3;   // same addr -> broadcast LDG
        lx = pw[0]; ly = pw[1]; lz = pw[2];
        if (tid == 0) {
            Q[(size_t)it*3]   = lx;
            Q[(size_t)it*3+1] = ly;
            Q[(size_t)it*3+2] = lz;
        }
    }
}

template<int PTS>
__global__ void __launch_bounds__(256) fps_fast(const float* __restrict__ pos,
                                                int n, int m,
                                                float* __restrict__ qpos)
{
    const int b = blockIdx.x;
    fps_body<PTS>(pos + (size_t)b * n * 3, n, m, qpos + (size_t)b * m * 3);
}

// =====================================================================
// Exact 64-NN SET body via 4-pass radix select on d2 float bits.
// Output slot order arbitrary (downstream max/any are order-invariant);
// SET matches lax.top_k exactly: all d2 < T plus smallest-index ties
// at d2 == T (T = exact 64th smallest; bits monotone for d2 >= 0).
// =====================================================================
template<int EPT>
__device__ __forceinline__ void knn_body(const float* __restrict__ S,
                                         float qx, float qy, float qz,
                                         int bq,
                                         int* __restrict__ nidx,
                                         float* __restrict__ nd2)
{
    __shared__ unsigned bins[256];
    __shared__ unsigned s_b, s_r;
    __shared__ int s_cnt, s_last;
    __shared__ unsigned s_min;
    const int tid = threadIdx.x;

    unsigned rb[EPT];
#pragma unroll
    for (int j = 0; j < EPT; j++) {
        int i = j*256 + tid;
        float dx = __fadd_rn(S[i*3],   -qx);
        float dy = __fadd_rn(S[i*3+1], -qy);
        float dz = __fadd_rn(S[i*3+2], -qz);
        rb[j] = __float_as_uint(__fadd_rn(__fadd_rn(__fmul_rn(dx,dx), __fmul_rn(dy,dy)),
                                          __fmul_rn(dz,dz)));
    }

    unsigned prefix = 0;
    unsigned rank = 64;
#pragma unroll
    for (int pass = 0; pass < 4; pass++) {
        const int shift = 24 - 8*pass;
        bins[tid] = 0;
        __syncthreads();
#pragma unroll
        for (int j = 0; j < EPT; j++) {
            unsigned v = rb[j];
            bool in = (pass == 0) ? true : ((v >> (shift + 8)) == prefix);
            if (in) atomicAdd(&bins[(v >> shift) & 255], 1u);
        }
        __syncthreads();
        if (tid < 32) {
            unsigned c[8]; unsigned ssum = 0;
#pragma unroll
            for (int t = 0; t < 8; t++) { c[t] = bins[tid*8 + t]; ssum += c[t]; }
            unsigned cum = ssum;
#pragma unroll
            for (int off = 1; off < 32; off <<= 1) {
                unsigned o = __shfl_up_sync(0xffffffffu, cum, off);
                if (tid >= off) cum += o;
            }
            unsigned excl = cum - ssum;
            if (rank > excl && rank <= cum) {
                unsigned rr = rank - excl;
#pragma unroll
                for (int t = 0; t < 8; t++) {
                    if (rr <= c[t]) { s_b = (unsigned)(tid*8 + t); s_r = rr; break; }
                    rr -= c[t];
                }
            }
        }
        __syncthreads();
        prefix = (prefix << 8) | s_b;
        rank = s_r;
        __syncthreads();
    }

    const unsigned T = prefix;
    const int take = (int)rank;

    if (tid == 0) { s_cnt = 0; s_last = -1; }
    __syncthreads();
#pragma unroll
    for (int j = 0; j < EPT; j++) {
        if (rb[j] < T) {
            int slot = atomicAdd(&s_cnt, 1);
            int i = j*256 + tid;
            nidx[(size_t)bq*KNN + slot] = i;
            nd2 [(size_t)bq*KNN + slot] = __uint_as_float(rb[j]);
        }
    }
    __syncthreads();
    const int c_less = s_cnt;
    for (int t = 0; t < take; t++) {
        if (tid == 0) s_min = 0xffffffffu;
        __syncthreads();
        int last = s_last;
#pragma unroll
        for (int j = 0; j < EPT; j++) {
            int i = j*256 + tid;
            if (rb[j] == T && i > last) atomicMin(&s_min, (unsigned)i);
        }
        __syncthreads();
        if (tid == 0) {
            int win = (int)s_min;
            s_last = win;
            nidx[(size_t)bq*KNN + c_less + t] = win;
            nd2 [(size_t)bq*KNN + c_less + t] = __uint_as_float(T);
        }
        __syncthreads();
    }
}

// =====================================================================
// MERGED kernel: blocks 0..3 run fps2 (qpos1 -> qpos2), blocks 4..8195
// run knn1 (xyz vs qpos1 -> nidx1, nd2_1). Both depend only on qpos1
// (complete before launch); they are mutually independent. Plain block
// role split — no polling, no occupancy caps.
// =====================================================================
__global__ void __launch_bounds__(256) knn1_fps2(const float* __restrict__ xyz)
{
    if (blockIdx.x < BATCH) {
        int b = blockIdx.x;
        fps_body<8>(g_qpos1 + (size_t)b * M1 * 3, M1, M2,
                    g_qpos2 + (size_t)b * M2 * 3);
        return;
    }
    int bq = blockIdx.x - BATCH;      // 0..8191
    int b  = bq >> 11;
    const float* S = xyz + (size_t)b * NPTS * 3;
    float qx = g_qpos1[(size_t)bq*3];
    float qy = g_qpos1[(size_t)bq*3 + 1];
    float qz = g_qpos1[(size_t)bq*3 + 2];
    knn_body<16>(S, qx, qy, qz, bq, g_nidx1, g_nd2_1);
}

// knn2 standalone
template<int EPT>
__global__ void __launch_bounds__(256) knn_select(const float* __restrict__ src,
                                                  const float* __restrict__ qpos,
                                                  int m,
                                                  int* __restrict__ nidx,
                                                  float* __restrict__ nd2)
{
    const int n = EPT * 256;
    const int bq = blockIdx.x;
    const int b  = bq / m;
    const float* S = src + (size_t)b * n * 3;
    float qx = qpos[(size_t)bq*3], qy = qpos[(size_t)bq*3+1], qz = qpos[(size_t)bq*3+2];
    knn_body<EPT>(S, qx, qy, qz, bq, nidx, nd2);
}

// =====================================================================
// Fully fused SA1 PointConv per query (round-11 exact): gather(6) ->
// Lin6x64+ReLU+BN -> Lin64x64+ReLU+BN -> dual-radius masked max.
// =====================================================================
__global__ void __launch_bounds__(128) sa1_fused(
    const float* __restrict__ color, const float* __restrict__ xyz,
    const float* __restrict__ w1a, const float* __restrict__ b1a,
    const float* __restrict__ g1a, const float* __restrict__ be1a,
    const float* __restrict__ w1b, const float* __restrict__ b1b,
    const float* __restrict__ g1b, const float* __restrict__ be1b)
{
    __shared__ __align__(16) float feats[64][6];
    __shared__ __align__(16) float Xs[64][66];
    __shared__ __align__(16) float Ws[64][66];
    __shared__ float d2s[64];
    __shared__ float redA[8][64];
    __shared__ float redB[8][64];

    const int bq = blockIdx.x;
    const int tid = threadIdx.x;
    const float bnf = 1.0f / sqrtf(1.0f + 1e-5f);

    if (tid < 64) {
        int r = bq*KNN + tid;
        int pt = g_nidx1[r];
        d2s[tid] = g_nd2_1[r];
        int b = bq >> 11;
        const float* cb = color + ((size_t)b*NPTS + pt) * 3;
        const float* pb = xyz   + ((size_t)b*NPTS + pt) * 3;
        const float* qp = g_qpos1 + (size_t)bq * 3;
        feats[tid][0] = cb[0]; feats[tid][1] = cb[1]; feats[tid][2] = cb[2];
        feats[tid][3] = pb[0] - qp[0];
        feats[tid][4] = pb[1] - qp[1];
        feats[tid][5] = pb[2] - qp[2];
    }
    for (int i = tid; i < 4096; i += 128) Ws[i >> 6][i & 63] = w1b[i];
    __syncthreads();

    {
        int row = tid >> 1;
        int cb0 = (tid & 1) * 32;
        float f0 = feats[row][0], f1 = feats[row][1], f2 = feats[row][2];
        float f3 = feats[row][3], f4 = feats[row][4], f5 = feats[row][5];
#pragma unroll 8
        for (int c = 0; c < 32; c++) {
            int col = cb0 + c;
            float acc = 0.f;
            acc = fmaf(f0, w1a[col],        acc);
            acc = fmaf(f1, w1a[64  + col],  acc);
            acc = fmaf(f2, w1a[128 + col],  acc);
            acc = fmaf(f3, w1a[192 + col],  acc);
            acc = fmaf(f4, w1a[256 + col],  acc);
            acc = fmaf(f5, w1a[320 + col],  acc);
            float v = fmaxf(acc + b1a[col], 0.f);
            Xs[col][row] = v * (g1a[col] * bnf) + be1a[col];
        }
    }
    __syncthreads();

    const int tn = (tid & 15) * 4;
    const int tm = (tid >> 4) * 8;
    unsigned long long acc[4][4];
#pragma unroll
    for (int i = 0; i < 4; i++)
#pragma unroll
        for (int j = 0; j < 4; j++) acc[i][j] = 0ull;

#pragma unroll 4
    for (int k = 0; k < 64; k++) {
        unsigned long long a2[4], b2[4];
#pragma unroll
        for (int i = 0; i < 4; i++)
            a2[i] = *(const unsigned long long*)&Xs[k][tm + 2*i];
#pragma unroll
        for (int j = 0; j < 4; j++) {
            float bv = Ws[k][tn + j];
            asm("mov.b64 %0, {%1, %1};" : "=l"(b2[j]) : "f"(bv));
        }
#pragma unroll
        for (int i = 0; i < 4; i++)
#pragma unroll
            for (int j = 0; j < 4; j++)
                asm("fma.rn.f32x2 %0, %1, %2, %0;"
                    : "+l"(acc[i][j]) : "l"(a2[i]), "l"(b2[j]));
    }

    const float rA = (float)(0.2*0.2), rB = (float)(0.1*0.1);
    const float NEG = -3.402823466e38f;
#pragma unroll
    for (int j = 0; j < 4; j++) {
        int col = tn + j;
        float s = g1b[col] * bnf, t = be1b[col], bi = b1b[col];
        float mA = NEG, mB = NEG;
#pragma unroll
        for (int i = 0; i < 4; i++) {
            float lo, hi; unpack2(acc[i][j], lo, hi);
            int r0 = tm + 2*i;
            float vlo = fmaxf(lo + bi, 0.f) * s + t;
            float vhi = fmaxf(hi + bi, 0.f) * s + t;
            float dA = d2s[r0], dB = d2s[r0+1];
            if (dA <= rA) mA = fmaxf(mA, vlo);
            if (dA <= rB) mB = fmaxf(mB, vlo);
            if (dB <= rA) mA = fmaxf(mA, vhi);
            if (dB <= rB) mB = fmaxf(mB, vhi);
        }
        redA[tid >> 4][col] = mA;
        redB[tid >> 4][col] = mB;
    }
    __syncthreads();
    if (tid < 64) {
        float a = NEG, c = NEG;
#pragma unroll
        for (int g = 0; g < 8; g++) {
            a = fmaxf(a, redA[g][tid]);
            c = fmaxf(c, redB[g][tid]);
        }
        g_x1[(size_t)bq*128 + tid]      = (a > -1e30f) ? a : 0.f;
        g_x1[(size_t)bq*128 + 64 + tid] = (c > -1e30f) ? c : 0.f;
    }
}

// =====================================================================
// SA2 layer-1 GEMM (K=131, N=128) with FUSED gather: each block covers
// exactly one query's 64 rows; nidx2 + rel-pos staged in smem; X rows
// gathered straight from g_x1 (L2-resident). Identical accumulation
// order to the old gather2+gemm path (zero-pad cols >= 131).
// =====================================================================
#define BKK 16
__global__ void __launch_bounds__(128) gemm_r2a(
    const float* __restrict__ W, const float* __restrict__ bias,
    const float* __restrict__ gamma, const float* __restrict__ beta)
{
    const int K = 131, N = 128;
    __shared__ __align__(16) float As[BKK][64 + 4];
    __shared__ __align__(16) float Bs[BKK][64 + 4];
    __shared__ int   s_ni[64];
    __shared__ float s_rel[64][3];
    const int tid = threadIdx.x;
    const int bq = blockIdx.y;              // 0..1639 (= b*M2 + q)
    const int bm = bq * 64, bn = blockIdx.x * 64;
    const int tn = (tid & 15) * 4;
    const int tm = (tid >> 4) * 8;

    if (tid < 64) {
        int w = bm + tid;
        int b = bq / M2;
        int n = g_nidx2[w];
        int na = b*M1 + n;
        s_ni[tid] = na;
#pragma unroll
        for (int c = 0; c < 3; c++)
            s_rel[tid][c] = g_qpos1[(size_t)na*3 + c] - g_qpos2[(size_t)bq*3 + c];
    }
    __syncthreads();

    unsigned long long acc[4][4];
#pragma unroll
    for (int i = 0; i < 4; i++)
#pragma unroll
        for (int j = 0; j < 4; j++) acc[i][j] = 0ull;

    for (int k0 = 0; k0 < K; k0 += BKK) {
#pragma unroll
        for (int i = 0; i < 8; i++) {
            int t = i*128 + tid;
            int m = t >> 4, k = t & 15;
            int gk = k0 + k;
            float v = 0.f;
            if (gk < 128)      v = g_x1[(size_t)s_ni[m]*128 + gk];
            else if (gk < 131) v = s_rel[m][gk - 128];
            As[k][m] = v;
        }
#pragma unroll
        for (int i = 0; i < 8; i++) {
            int t = i*128 + tid;
            int k = t >> 6, n = t & 63;
            int gk = k0 + k;
            float v = 0.f;
            if (gk < K) v = W[(size_t)gk*N + bn + n];
            Bs[k][n] = v;
        }
        __syncthreads();
#pragma unroll
        for (int kk = 0; kk < BKK; kk++) {
            unsigned long long a2[4], b2[4];
#pragma unroll
            for (int i = 0; i < 4; i++)
                a2[i] = *(const unsigned long long*)&As[kk][tm + 2*i];
#pragma unroll
            for (int j = 0; j < 4; j++) {
                float bv = Bs[kk][tn + j];
                asm("mov.b64 %0, {%1, %1};" : "=l"(b2[j]) : "f"(bv));
            }
#pragma unroll
            for (int i = 0; i < 4; i++)
#pragma unroll
                for (int j = 0; j < 4; j++)
                    asm("fma.rn.f32x2 %0, %1, %2, %0;"
                        : "+l"(acc[i][j]) : "l"(a2[i]), "l"(b2[j]));
        }
        __syncthreads();
    }

    const float bnf = 1.0f / sqrtf(1.0f + 1e-5f);
#pragma unroll
    for (int j = 0; j < 4; j++) {
        int c = bn + tn + j;
        float s = gamma[c] * bnf, t = beta[c], bi = bias[c];
#pragma unroll
        for (int i = 0; i < 4; i++) {
            float lo, hi; unpack2(acc[i][j], lo, hi);
            int r0 = bm + tm + 2*i;
            float vlo = fmaxf(lo + bi, 0.f);
            g_bufA[(size_t)r0*N + bn + tn + j] = vlo * s + t;
            float vhi = fmaxf(hi + bi, 0.f);
            g_bufA[(size_t)(r0+1)*N + bn + tn + j] = vhi * s + t;
        }
    }
}

// =====================================================================
// SA2 layer-2 GEMM (K=128, N=256) with FUSED dual-radius masked max.
// =====================================================================
__global__ void __launch_bounds__(128) gemm_bn_max2(const float* __restrict__ X,
    const float* __restrict__ W, const float* __restrict__ bias,
    const float* __restrict__ gamma, const float* __restrict__ beta)
{
    __shared__ __align__(16) float As[BKK][64 + 4];
    __shared__ __align__(16) float Bs[BKK][64 + 4];
    __shared__ float d2s[64];
    __shared__ float redA[8][64];
    __shared__ float redB[8][64];
    const int K = 128, N = 256;
    const int tid = threadIdx.x;
    const int bq = blockIdx.y;
    const int bm = bq * 64, bn = blockIdx.x * 64;
    const int tn = (tid & 15) * 4;
    const int tm = (tid >> 4) * 8;

    if (tid < 64) d2s[tid] = g_nd2_2[(size_t)bq*KNN + tid];

    unsigned long long acc[4][4];
#pragma unroll
    for (int i = 0; i < 4; i++)
#pragma unroll
        for (int j = 0; j < 4; j++) acc[i][j] = 0ull;

    for (int k0 = 0; k0 < K; k0 += BKK) {
#pragma unroll
        for (int i = 0; i < 8; i++) {
            int t = i*128 + tid;
            int m = t >> 4, k = t & 15;
            As[k][m] = X[(size_t)(bm + m)*K + k0 + k];
        }
#pragma unroll
        for (int i = 0; i < 8; i++) {
            int t = i*128 + tid;
            int k = t >> 6, n = t & 63;
            Bs[k][n] = W[(size_t)(k0 + k)*N + bn + n];
        }
        __syncthreads();
#pragma unroll
        for (int kk = 0; kk < BKK; kk++) {
            unsigned long long a2[4], b2[4];
#pragma unroll
            for (int i = 0; i < 4; i++)
                a2[i] = *(const unsigned long long*)&As[kk][tm + 2*i];
#pragma unroll
            for (int j = 0; j < 4; j++) {
                float bv = Bs[kk][tn + j];
                asm("mov.b64 %0, {%1, %1};" : "=l"(b2[j]) : "f"(bv));
            }
#pragma unroll
            for (int i = 0; i < 4; i++)
#pragma unroll
                for (int j = 0; j < 4; j++)
                    asm("fma.rn.f32x2 %0, %1, %2, %0;"
                        : "+l"(acc[i][j]) : "l"(a2[i]), "l"(b2[j]));
        }
        __syncthreads();
    }

    const float bnf = 1.0f / sqrtf(1.0f + 1e-5f);
    const float rA = (float)(0.35*0.35), rB = (float)(0.5*0.5);
    const float NEG = -3.402823466e38f;
#pragma unroll
    for (int j = 0; j < 4; j++) {
        int c = bn + tn + j;
        float s = gamma[c] * bnf, t = beta[c], bi = bias[c];
        float mA = NEG, mB = NEG;
#pragma unroll
        for (int i = 0; i < 4; i++) {
            float lo, hi; unpack2(acc[i][j], lo, hi);
            int r0 = tm + 2*i;
            float vlo = fmaxf(lo + bi, 0.f) * s + t;
            float vhi = fmaxf(hi + bi, 0.f) * s + t;
            float dA = d2s[r0], dB = d2s[r0+1];
            if (dA <= rA) mA = fmaxf(mA, vlo);
            if (dA <= rB) mB = fmaxf(mB, vlo);
            if (dB <= rA) mA = fmaxf(mA, vhi);
            if (dB <= rB) mB = fmaxf(mB, vhi);
        }
        redA[tid >> 4][tn + j] = mA;
        redB[tid >> 4][tn + j] = mB;
    }
    __syncthreads();
    if (tid < 64) {
        float a = NEG, c = NEG;
#pragma unroll
        for (int g = 0; g < 8; g++) {
            a = fmaxf(a, redA[g][tid]);
            c = fmaxf(c, redB[g][tid]);
        }
        g_x2[(size_t)bq*512 + bn + tid]       = (a > -1e30f) ? a : 0.f;
        g_x2[(size_t)bq*512 + 256 + bn + tid] = (c > -1e30f) ? c : 0.f;
    }
}

// =====================================================================
// mlp3 GEMM (M=1640, K=515, N=1024) with FUSED gather3 in the X loader.
// =====================================================================
__global__ void __launch_bounds__(128) gemm_r3(
    const float* __restrict__ W, const float* __restrict__ bias,
    const float* __restrict__ gamma, const float* __restrict__ beta)
{
    const int M = R3, K = 515, N = 1024;
    __shared__ __align__(16) float As[BKK][64 + 4];
    __shared__ __align__(16) float Bs[BKK][64 + 4];
    const int tid = threadIdx.x;
    const int bm = blockIdx.y * 64, bn = blockIdx.x * 64;
    const int tn = (tid & 15) * 4;
    const int tm = (tid >> 4) * 8;

    unsigned long long acc[4][4];
#pragma unroll
    for (int i = 0; i < 4; i++)
#pragma unroll
        for (int j = 0; j < 4; j++) acc[i][j] = 0ull;

    for (int k0 = 0; k0 < K; k0 += BKK) {
#pragma unroll
        for (int i = 0; i < 8; i++) {
            int t = i*128 + tid;
            int m = t >> 4, k = t & 15;
            int gr = bm + m, gk = k0 + k;
            float v = 0.f;
            if (gr < M) {
                if (gk < 512)      v = g_x2[(size_t)gr*512 + gk];
                else if (gk < 515) v = g_qpos2[(size_t)gr*3 + (gk - 512)];
            }
            As[k][m] = v;
        }
#pragma unroll
        for (int i = 0; i < 8; i++) {
            int t = i*128 + tid;
            int k = t >> 6, n = t & 63;
            int gk = k0 + k;
            float v = 0.f;
            if (gk < K) v = W[(size_t)gk*N + bn + n];
            Bs[k][n] = v;
        }
        __syncthreads();
#pragma unroll
        for (int kk = 0; kk < BKK; kk++) {
            unsigned long long a2[4], b2[4];
#pragma unroll
            for (int i = 0; i < 4; i++)
                a2[i] = *(const unsigned long long*)&As[kk][tm + 2*i];
#pragma unroll
            for (int j = 0; j < 4; j++) {
                float bv = Bs[kk][tn + j];
                asm("mov.b64 %0, {%1, %1};" : "=l"(b2[j]) : "f"(bv));
            }
#pragma unroll
            for (int i = 0; i < 4; i++)
#pragma unroll
                for (int j = 0; j < 4; j++)
                    asm("fma.rn.f32x2 %0, %1, %2, %0;"
                        : "+l"(acc[i][j]) : "l"(a2[i]), "l"(b2[j]));
        }
        __syncthreads();
    }

    const float bnf = 1.0f / sqrtf(1.0f + 1e-5f);
#pragma unroll
    for (int j = 0; j < 4; j++) {
        int c = bn + tn + j;
        float s = gamma[c] * bnf, t = beta[c], bi = bias[c];
#pragma unroll
        for (int i = 0; i < 4; i++) {
            float lo, hi; unpack2(acc[i][j], lo, hi);
            int r0 = bm + tm + 2*i;
            if (r0 < M) {
                float v = fmaxf(lo + bi, 0.f);
                g_bufA[(size_t)r0*N + bn + tn + j] = v * s + t;
            }
            if (r0 + 1 < M) {
                float v = fmaxf(hi + bi, 0.f);
                g_bufA[(size_t)(r0+1)*N + bn + tn + j] = v * s + t;
            }
        }
    }
}

__global__ void globalmax_kernel()
{
    int f = blockIdx.x * 256 + threadIdx.x;
    int b = blockIdx.y;
    float m = -3.402823466e38f;
    for (int q = 0; q < M2; q++)
        m = fmaxf(m, g_bufA[((size_t)(b*M2 + q))*1024 + f]);
    g_glob[(size_t)b*1024 + f] = m;
}

// =====================================================================
// Head: h1 = relu(g @ wl1 + bl1); out = h1 @ wl2 + bl2; L2-normalize.
// =====================================================================
__global__ void __launch_bounds__(512) head_kernel(
    const float* __restrict__ wl1, const float* __restrict__ bl1,
    const float* __restrict__ wl2, const float* __restrict__ bl2,
    float* __restrict__ out)
{
    __shared__ float sg[1024];
    __shared__ float sh[512];
    __shared__ float so[128];
    __shared__ float snorm;
    int b = blockIdx.x, tid = threadIdx.x;
    sg[tid]       = g_glob[(size_t)b*1024 + tid];
    sg[tid + 512] = g_glob[(size_t)b*1024 + 512 + tid];
    __syncthreads();

    float acc = bl1[tid];
    for (int k = 0; k < 1024; k++) acc = fmaf(sg[k], wl1[(size_t)k*512 + tid], acc);
    sh[tid] = fmaxf(acc, 0.f);
    __syncthreads();

    if (tid < 128) {
        float o = bl2[tid];
        for (int k = 0; k < 512; k++) o = fmaf(sh[k], wl2[(size_t)k*128 + tid], o);
        so[tid] = o;
    }
    __syncthreads();
    if (tid < 32) {
        float s = 0.f;
        for (int c = tid; c < 128; c += 32) s += so[c] * so[c];
#pragma unroll
        for (int off = 16; off > 0; off >>= 1) s += __shfl_down_sync(0xffffffffu, s, off);
        if (tid == 0) snorm = sqrtf(s);
    }
    __syncthreads();
    if (tid < 128) out[(size_t)b*128 + tid] = so[tid] / snorm;
}

// =====================================================================
extern "C" void kernel_launch(void* const* d_in, const int* in_sizes, int n_in,
                              void* d_out, int out_size)
{
    const float* xyz   = (const float*)d_in[0];
    const float* color = (const float*)d_in[1];
    const float* w1a = (const float*)d_in[2],  *b1a = (const float*)d_in[3];
    const float* g1a = (const float*)d_in[4],  *be1a = (const float*)d_in[5];
    const float* w1b = (const float*)d_in[6],  *b1b = (const float*)d_in[7];
    const float* g1b = (const float*)d_in[8],  *be1b = (const float*)d_in[9];
    const float* w2a = (const float*)d_in[10], *b2a = (const float*)d_in[11];
    const float* g2a = (const float*)d_in[12], *be2a = (const float*)d_in[13];
    const float* w2b = (const float*)d_in[14], *b2b = (const float*)d_in[15];
    const float* g2b = (const float*)d_in[16], *be2b = (const float*)d_in[17];
    const float* w3  = (const float*)d_in[18], *b3  = (const float*)d_in[19];
    const float* g3  = (const float*)d_in[20], *be3 = (const float*)d_in[21];
    const float* wl1 = (const float*)d_in[22], *bl1 = (const float*)d_in[23];
    const float* wl2 = (const float*)d_in[24], *bl2 = (const float*)d_in[25];
    float* out = (float*)d_out;

    void *vQ1, *vQ2, *vN2, *vD2, *vA;
    cudaGetSymbolAddress(&vQ1, g_qpos1);
    cudaGetSymbolAddress(&vQ2, g_qpos2);
    cudaGetSymbolAddress(&vN2, g_nidx2);
    cudaGetSymbolAddress(&vD2, g_nd2_2);
    cudaGetSymbolAddress(&vA, g_bufA);
    float* aQ1 = (float*)vQ1; float* aQ2 = (float*)vQ2;
    int* aN2 = (int*)vN2; float* aD2 = (float*)vD2;
    float* aA = (float*)vA;

    // ---- fps1, then fps2 merged with knn1 (mutually independent) ----
    fps_fast<16><<<BATCH, 256>>>(xyz, NPTS, M1, aQ1);
    knn1_fps2<<<BATCH + BATCH*M1, 256>>>(xyz);

    // ---- knn2 + fused SA1 conv ----
    knn_select<8><<<BATCH*M2, 256>>>(aQ1, aQ2, M2, aN2, aD2);
    sa1_fused<<<BATCH*M1, 128>>>(color, xyz, w1a, b1a, g1a, be1a,
                                 w1b, b1b, g1b, be1b);

    // ---- SA2 GEMMs (gather fused into R2a) ----
    gemm_r2a<<<dim3(2, R2/64), 128>>>(w2a, b2a, g2a, be2a);
    gemm_bn_max2<<<dim3(4, R2/64), 128>>>(aA, w2b, b2b, g2b, be2b);

    // ---- mlp3 (gather fused) + global max + head ----
    gemm_r3<<<dim3(16, (R3 + 63)/64), 128>>>(w3, b3, g3, be3);
    globalmax_kernel<<<dim3(4, BATCH), 256>>>();
    head_kernel<<<BATCH, 512>>>(wl1, bl1, wl2, bl2, out);
}